// round 1
// baseline (speedup 1.0000x reference)
#include <cuda_runtime.h>
#include <math.h>

// Problem geometry (fixed by the reference: (2,1,192,192,192) fp32 x3 -> scalar)
constexpr int BATCH = 2;
constexpr int D = 192, H = 192, W = 192;
constexpr int TX = 32;        // tile width  (x, contiguous)
constexpr int TY = 16;        // tile height (y)
constexpr int ZC = 48;        // z planes per block
constexpr int NZ = D / ZC;    // 4 z-chunks
constexpr double NTOT = (double)BATCH * D * H * W;

__device__ double g_accum;

__global__ void k_zero() { g_accum = 0.0; }

struct Plane { float A, Bx, By; };

// Hardware tanh (sm_75+): ~2^-11 abs error, exact where tanh saturates.
__device__ __forceinline__ float htanh(float x) {
    float y;
    asm("tanh.approx.f32 %0, %1;" : "=f"(y) : "f"(x));
    return y;
}

// Stage 1: per-row x-pass for plane zz. Writes smooth (sx) and diff (dx) rows
// covering y-halo rows [by-1, by+TY] into shared buffers. Zero-pad OOB.
__device__ __forceinline__ void stage1(const float* __restrict__ img, int gx, int zz, int by,
                                       int tx, int ty,
                                       float (*sx)[TX], float (*dx)[TX]) {
    const bool zok = (unsigned)zz < (unsigned)D;
    const float* pl = img + (size_t)zz * (H * W);
#pragma unroll
    for (int k = 0; k < 2; k++) {
        int r = ty + k * TY;
        if (r < TY + 2) {
            int gy = by + r - 1;
            float vm = 0.f, vc = 0.f, vp = 0.f;
            if (zok && (unsigned)gy < (unsigned)H) {
                const float* row = pl + (size_t)gy * W;
                vc = __ldg(row + gx);
                if (gx > 0)     vm = __ldg(row + gx - 1);
                if (gx < W - 1) vp = __ldg(row + gx + 1);
            }
            sx[r][tx] = fmaf(2.f, vc, vm + vp);
            dx[r][tx] = vp - vm;
        }
    }
}

// Stage 2: fold the 3 y-neighbor rows into per-plane partials.
__device__ __forceinline__ Plane stage2(int tx, int ty,
                                        const float (*sx)[TX], const float (*dx)[TX]) {
    float s0 = sx[ty][tx], s1 = sx[ty + 1][tx], s2 = sx[ty + 2][tx];
    float d0 = dx[ty][tx], d1 = dx[ty + 1][tx], d2 = dx[ty + 2][tx];
    Plane p;
    p.A  = fmaf(2.f, s1, s0 + s2);  // smooth_y(smooth_x)
    p.By = s0 - s2;                 // diff_y(smooth_x)
    p.Bx = fmaf(2.f, d1, d0 + d2);  // smooth_y(diff_x)
    return p;
}

__global__ __launch_bounds__(TX * TY)
void k_loss(const float* __restrict__ pred,
            const float* __restrict__ gt,
            const float* __restrict__ mask) {
    __shared__ float sxP[TY + 2][TX], dxP[TY + 2][TX];
    __shared__ float sxG[TY + 2][TX], dxG[TY + 2][TX];
    __shared__ float warpsum[(TX * TY) / 32];

    const int tx = threadIdx.x, ty = threadIdx.y;
    const int gx = blockIdx.x * TX + tx;       // always < W (192 % 32 == 0)
    const int by = blockIdx.y * TY;
    const int gy = by + ty;
    const int b  = blockIdx.z / NZ;
    const int z0 = (blockIdx.z % NZ) * ZC;

    const size_t base = (size_t)b * D * H * W;
    const float* P = pred + base;
    const float* G = gt   + base;
    const float* M = mask + base;

    Plane p0, p1, p2, g0, g1, g2;

    // Prologue: planes z0-1 and z0 into ring slots 0,1
    stage1(P, gx, z0 - 1, by, tx, ty, sxP, dxP);
    stage1(G, gx, z0 - 1, by, tx, ty, sxG, dxG);
    __syncthreads();
    p0 = stage2(tx, ty, sxP, dxP);
    g0 = stage2(tx, ty, sxG, dxG);
    __syncthreads();
    stage1(P, gx, z0, by, tx, ty, sxP, dxP);
    stage1(G, gx, z0, by, tx, ty, sxG, dxG);
    __syncthreads();
    p1 = stage2(tx, ty, sxP, dxP);
    g1 = stage2(tx, ty, sxG, dxG);

    float acc = 0.f;
    for (int z = z0; z < z0 + ZC; z++) {
        __syncthreads();                       // protect smem vs prior stage2 reads
        stage1(P, gx, z + 1, by, tx, ty, sxP, dxP);
        stage1(G, gx, z + 1, by, tx, ty, sxG, dxG);
        __syncthreads();
        p2 = stage2(tx, ty, sxP, dxP);
        g2 = stage2(tx, ty, sxG, dxG);

        // z-combine (signs irrelevant: squared below)
        float gxp = fmaf(2.f, p1.Bx, p0.Bx + p2.Bx);
        float gyp = fmaf(2.f, p1.By, p0.By + p2.By);
        float gzp = p0.A - p2.A;
        float magp = sqrtf(fmaf(gxp, gxp, fmaf(gyp, gyp, fmaf(gzp, gzp, 1e-10f))));

        float gxg = fmaf(2.f, g1.Bx, g0.Bx + g2.Bx);
        float gyg = fmaf(2.f, g1.By, g0.By + g2.By);
        float gzg = g0.A - g2.A;
        float magg = sqrtf(fmaf(gxg, gxg, fmaf(gyg, gyg, fmaf(gzg, gzg, 1e-10f))));

        size_t idx = ((size_t)z * H + gy) * W + gx;
        float pv = __ldg(P + idx), gv = __ldg(G + idx), mv = __ldg(M + idx);
        float d   = pv - gv;
        float mse = d * d * mv;
        float dm  = magg - magp;
        float mge = dm * dm * mv;
        acc += fmaf(htanh(mge), mse, mse);

        p0 = p1; p1 = p2;
        g0 = g1; g1 = g2;
    }

    // Block reduction -> one fp64 atomic per block
#pragma unroll
    for (int o = 16; o; o >>= 1) acc += __shfl_xor_sync(0xffffffffu, acc, o);
    const int tid = ty * TX + tx;
    const int wid = tid >> 5, lane = tid & 31;
    if (lane == 0) warpsum[wid] = acc;
    __syncthreads();
    if (wid == 0) {
        float v = (lane < (TX * TY) / 32) ? warpsum[lane] : 0.f;
#pragma unroll
        for (int o = 8; o; o >>= 1) v += __shfl_xor_sync(0xffffffffu, v, o);
        if (lane == 0) atomicAdd(&g_accum, (double)v);
    }
}

__global__ void k_final(float* out) { out[0] = (float)(g_accum / NTOT); }

extern "C" void kernel_launch(void* const* d_in, const int* in_sizes, int n_in,
                              void* d_out, int out_size) {
    const float* pred = (const float*)d_in[0];
    const float* gt   = (const float*)d_in[1];
    const float* mask = (const float*)d_in[2];
    float* out = (float*)d_out;

    k_zero<<<1, 1>>>();
    dim3 grid(W / TX, H / TY, BATCH * NZ);   // (6, 12, 8) = 576 blocks
    dim3 block(TX, TY);                      // 512 threads
    k_loss<<<grid, block>>>(pred, gt, mask);
    k_final<<<1, 1>>>(out);
}

// round 2
// speedup vs baseline: 2.4434x; 2.4434x over previous
#include <cuda_runtime.h>

// Geometry fixed by the reference: (2,1,192,192,192) fp32 x3 -> scalar
constexpr int BATCH = 2, D = 192, H = 192, W = 192;
constexpr int XV = 4;                 // x-values per thread (one float4)
constexpr int ZC = 16;                // z planes per thread
constexpr int GX = W / XV;            // 48
constexpr int NZ = D / ZC;            // 12
constexpr int THREADS = 128;
constexpr long long NVOX = (long long)BATCH * D * H * W;
constexpr int TOTAL_THREADS = BATCH * H * GX * NZ;     // 221184
constexpr int NBLOCKS = TOTAL_THREADS / THREADS;       // 1728

__device__ double   g_accum = 0.0;
__device__ unsigned g_done  = 0;

__device__ __forceinline__ float fsqrt_a(float x) {
    float y; asm("sqrt.approx.f32 %0, %1;" : "=f"(y) : "f"(x)); return y;
}
__device__ __forceinline__ float htanh(float x) {
    float y; asm("tanh.approx.f32 %0, %1;" : "=f"(y) : "f"(x)); return y;
}

// Load 6-wide x-window (halo-1 .. halo+4) of one row; zero-pad OOB.
__device__ __forceinline__ void load6(const float* __restrict__ pl, int gy, int x0, float v[6]) {
    v[0] = v[1] = v[2] = v[3] = v[4] = v[5] = 0.f;
    if ((unsigned)gy < (unsigned)H) {
        const float* row = pl + (size_t)gy * W;
        float4 c = __ldg(reinterpret_cast<const float4*>(row + x0));
        v[1] = c.x; v[2] = c.y; v[3] = c.z; v[4] = c.w;
        if (x0 > 0)      v[0] = __ldg(row + x0 - 1);
        if (x0 + XV < W) v[5] = __ldg(row + x0 + XV);
    }
}

// One z-plane of one image: in-plane separable pass.
// A  = smooth_y(smooth_x)   (feeds gz = A[z-1]-A[z+1])
// Bx = smooth_y(diff_x)     (feeds gx = [1,2,1]_z * Bx)
// By = diff_y(smooth_x)     (feeds gy = [1,2,1]_z * By)
// C  = raw center values (for the MSE term)
__device__ __forceinline__ void plane_pass(const float* __restrict__ img, int zz, int gy, int x0,
                                           float A[XV], float Bx[XV], float By[XV], float C[XV]) {
    if ((unsigned)zz >= (unsigned)D) {
#pragma unroll
        for (int j = 0; j < XV; j++) { A[j] = Bx[j] = By[j] = C[j] = 0.f; }
        return;
    }
    const float* pl = img + (size_t)zz * (H * W);
    float v0[6], v1[6], v2[6];
    load6(pl, gy - 1, x0, v0);
    load6(pl, gy,     x0, v1);
    load6(pl, gy + 1, x0, v2);
#pragma unroll
    for (int j = 0; j < XV; j++) {
        float s0 = fmaf(2.f, v0[j + 1], v0[j] + v0[j + 2]);
        float s1 = fmaf(2.f, v1[j + 1], v1[j] + v1[j + 2]);
        float s2 = fmaf(2.f, v2[j + 1], v2[j] + v2[j + 2]);
        float d0 = v0[j + 2] - v0[j];
        float d1 = v1[j + 2] - v1[j];
        float d2 = v2[j + 2] - v2[j];
        A[j]  = fmaf(2.f, s1, s0 + s2);
        By[j] = s0 - s2;
        Bx[j] = fmaf(2.f, d1, d0 + d2);
        C[j]  = v1[j + 1];
    }
}

__global__ void __launch_bounds__(THREADS, 3)
k_loss(const float* __restrict__ pred,
       const float* __restrict__ gt,
       const float* __restrict__ mask,
       float* __restrict__ out) {
    int t   = blockIdx.x * THREADS + threadIdx.x;
    int xg  = t % GX;
    int tmp = t / GX;
    int gy  = tmp % H;  tmp /= H;
    int zc  = tmp % NZ;
    int b   = tmp / NZ;
    int x0  = xg * XV;
    int z0  = zc * ZC;

    const size_t base = (size_t)b * D * H * W;
    const float* P = pred + base;
    const float* G = gt   + base;
    const float* M = mask + base;

    float pA[3][XV], pBx[3][XV], pBy[3][XV];
    float gA[3][XV], gBx[3][XV], gBy[3][XV];
    float cP[XV], cG[XV], dum[XV];

    // Prologue: planes z0-1 (slot 0) and z0 (slot 1)
    plane_pass(P, z0 - 1, gy, x0, pA[0], pBx[0], pBy[0], dum);
    plane_pass(G, z0 - 1, gy, x0, gA[0], gBx[0], gBy[0], dum);
    plane_pass(P, z0,     gy, x0, pA[1], pBx[1], pBy[1], cP);
    plane_pass(G, z0,     gy, x0, gA[1], gBx[1], gBy[1], cG);

    float acc = 0.f;
    for (int c = z0; c < z0 + ZC; c++) {
        float cPn[XV], cGn[XV];
        plane_pass(P, c + 1, gy, x0, pA[2], pBx[2], pBy[2], cPn);
        plane_pass(G, c + 1, gy, x0, gA[2], gBx[2], gBy[2], cGn);

        float4 m4 = __ldg(reinterpret_cast<const float4*>(M + ((size_t)c * H + gy) * W + x0));
        float mv[XV] = { m4.x, m4.y, m4.z, m4.w };

#pragma unroll
        for (int j = 0; j < XV; j++) {
            float gxp = fmaf(2.f, pBx[1][j], pBx[0][j] + pBx[2][j]);
            float gyp = fmaf(2.f, pBy[1][j], pBy[0][j] + pBy[2][j]);
            float gzp = pA[0][j] - pA[2][j];
            float magp = fsqrt_a(fmaf(gxp, gxp, fmaf(gyp, gyp, fmaf(gzp, gzp, 1e-10f))));

            float gxg = fmaf(2.f, gBx[1][j], gBx[0][j] + gBx[2][j]);
            float gyg = fmaf(2.f, gBy[1][j], gBy[0][j] + gBy[2][j]);
            float gzg = gA[0][j] - gA[2][j];
            float magg = fsqrt_a(fmaf(gxg, gxg, fmaf(gyg, gyg, fmaf(gzg, gzg, 1e-10f))));

            float d   = cP[j] - cG[j];
            float mse = d * d * mv[j];
            float dm  = magg - magp;
            float mge = dm * dm * mv[j];
            acc += fmaf(htanh(mge), mse, mse);
        }

        // rotate register rings
#pragma unroll
        for (int j = 0; j < XV; j++) {
            pA[0][j]  = pA[1][j];  pA[1][j]  = pA[2][j];
            pBx[0][j] = pBx[1][j]; pBx[1][j] = pBx[2][j];
            pBy[0][j] = pBy[1][j]; pBy[1][j] = pBy[2][j];
            gA[0][j]  = gA[1][j];  gA[1][j]  = gA[2][j];
            gBx[0][j] = gBx[1][j]; gBx[1][j] = gBx[2][j];
            gBy[0][j] = gBy[1][j]; gBy[1][j] = gBy[2][j];
            cP[j] = cPn[j]; cG[j] = cGn[j];
        }
    }

    // Block reduction -> one fp64 atomic, last block finalizes + resets state
#pragma unroll
    for (int o = 16; o; o >>= 1) acc += __shfl_xor_sync(0xffffffffu, acc, o);
    __shared__ float ws[THREADS / 32];
    int lane = threadIdx.x & 31, wid = threadIdx.x >> 5;
    if (lane == 0) ws[wid] = acc;
    __syncthreads();
    if (threadIdx.x == 0) {
        float s = ws[0] + ws[1] + ws[2] + ws[3];
        atomicAdd(&g_accum, (double)s);
        __threadfence();
        unsigned tk = atomicAdd(&g_done, 1u);
        if (tk == (unsigned)gridDim.x - 1u) {
            double total = atomicAdd(&g_accum, 0.0);   // L2-coherent read
            out[0] = (float)(total / (double)NVOX);
            g_accum = 0.0;                              // re-arm for next graph replay
            g_done  = 0;
        }
    }
}

extern "C" void kernel_launch(void* const* d_in, const int* in_sizes, int n_in,
                              void* d_out, int out_size) {
    const float* pred = (const float*)d_in[0];
    const float* gt   = (const float*)d_in[1];
    const float* mask = (const float*)d_in[2];
    k_loss<<<NBLOCKS, THREADS>>>(pred, gt, mask, (float*)d_out);
}